// round 6
// baseline (speedup 1.0000x reference)
#include <cuda_runtime.h>
#include <cuda_bf16.h>
#include <math.h>

#define N_NODES 10000
#define N_EDGES 160000
#define N_GRAPHS 64
#define HID 128
#define LAT 64
#define NLAY 3
#define ET 64          // edges per block in the edge kernel
#define NB 8           // nodes per block in node_kernel

// ---------------- device scratch (no allocations allowed) ----------------
__device__ float d_h[N_NODES * HID];
__device__ float d_aggr[N_NODES * HID];
// B-fragment packed weights: per (layer, kstep, ntile, lane) a uint4 {hi01, hi89, lo01, lo89}
__device__ uint4 d_W1f[NLAY * 16 * 32 * 32];   // GEMM1: K=256 (16 steps), N=256 (32 ntiles)
__device__ uint4 d_W2f[NLAY * 16 * 16 * 32];   // GEMM2: K=256 (16 steps), N=128 (16 ntiles)
__device__ float d_W1tail[NLAY * 256];         // k=256 column (edge_attr weight)
__device__ float d_Wgt[NLAY * 256 * HID];      // gate_W transposed
__device__ float d_sums[N_GRAPHS * HID];
__device__ float d_counts[N_GRAPHS];

__device__ __forceinline__ float sigmoidf_(float v) {
    return 1.f / (1.f + __expf(-v));
}
// pack two floats into bf16x2 (lo = first element)
__device__ __forceinline__ unsigned pk2(float lo, float hi) {
    unsigned r;
    asm("cvt.rn.bf16x2.f32 %0, %1, %2;" : "=r"(r) : "f"(hi), "f"(lo));
    return r;
}
__device__ __forceinline__ void mma_bf16(float c[4],
                                         unsigned a0, unsigned a1, unsigned a2, unsigned a3,
                                         unsigned b0, unsigned b1) {
    asm("mma.sync.aligned.m16n8k16.row.col.f32.bf16.bf16.f32 "
        "{%0,%1,%2,%3}, {%4,%5,%6,%7}, {%8,%9}, {%0,%1,%2,%3};"
        : "+f"(c[0]), "+f"(c[1]), "+f"(c[2]), "+f"(c[3])
        : "r"(a0), "r"(a1), "r"(a2), "r"(a3), "r"(b0), "r"(b1));
}
__device__ __forceinline__ void ldsm4(unsigned r[4], unsigned addr) {
    asm volatile("ldmatrix.sync.aligned.m8n8.x4.shared.b16 {%0,%1,%2,%3}, [%4];"
        : "=r"(r[0]), "=r"(r[1]), "=r"(r[2]), "=r"(r[3]) : "r"(addr));
}

__device__ __forceinline__ float block_sum128(float v, float* red, int j) {
    red[j] = v;
    __syncthreads();
    #pragma unroll
    for (int s = 64; s > 0; s >>= 1) {
        if (j < s) red[j] += red[j + s];
        __syncthreads();
    }
    float r = red[0];
    __syncthreads();
    return r;
}

// ---------------- weight fragment packing (run once per launch) ----------------
__global__ void pack_kernel(const float* __restrict__ W1,   // [3][256][257]
                            const float* __restrict__ W2,   // [3][128][256]
                            const float* __restrict__ Wg) { // [3][128][256]
    int idx = blockIdx.x * blockDim.x + threadIdx.x;
    int stride = gridDim.x * blockDim.x;
    const int n1 = NLAY * 16 * 32 * 32;
    for (int t = idx; t < n1; t += stride) {
        int l = t / (16 * 32 * 32);
        int r = t % (16 * 32 * 32);
        int s = r / (32 * 32);
        int r2 = r % (32 * 32);
        int tt = r2 / 32;
        int lane = r2 % 32;
        int n = tt * 8 + lane / 4;
        int k0 = s * 16 + (lane % 4) * 2;
        const float* row = W1 + (l * 256 + n) * 257;
        float f0 = row[k0], f1 = row[k0 + 1], f2 = row[k0 + 8], f3 = row[k0 + 9];
        unsigned h01 = pk2(f0, f1);
        unsigned h89 = pk2(f2, f3);
        float a0 = __uint_as_float(h01 << 16), a1 = __uint_as_float(h01 & 0xFFFF0000u);
        float a2 = __uint_as_float(h89 << 16), a3 = __uint_as_float(h89 & 0xFFFF0000u);
        uint4 o;
        o.x = h01; o.y = h89;
        o.z = pk2(f0 - a0, f1 - a1);
        o.w = pk2(f2 - a2, f3 - a3);
        d_W1f[t] = o;
    }
    const int n2 = NLAY * 16 * 16 * 32;
    for (int t = idx; t < n2; t += stride) {
        int l = t / (16 * 16 * 32);
        int r = t % (16 * 16 * 32);
        int s = r / (16 * 32);
        int r2 = r % (16 * 32);
        int tt = r2 / 32;
        int lane = r2 % 32;
        int n = tt * 8 + lane / 4;
        int k0 = s * 16 + (lane % 4) * 2;
        const float* row = W2 + (l * 128 + n) * 256;
        float f0 = row[k0], f1 = row[k0 + 1], f2 = row[k0 + 8], f3 = row[k0 + 9];
        unsigned h01 = pk2(f0, f1);
        unsigned h89 = pk2(f2, f3);
        float a0 = __uint_as_float(h01 << 16), a1 = __uint_as_float(h01 & 0xFFFF0000u);
        float a2 = __uint_as_float(h89 << 16), a3 = __uint_as_float(h89 & 0xFFFF0000u);
        uint4 o;
        o.x = h01; o.y = h89;
        o.z = pk2(f0 - a0, f1 - a1);
        o.w = pk2(f2 - a2, f3 - a3);
        d_W2f[t] = o;
    }
    for (int t = idx; t < NLAY * 256; t += stride) {
        int l = t / 256;
        int j = t % 256;
        d_W1tail[t] = W1[(l * 256 + j) * 257 + 256];
    }
    const int n3 = NLAY * 128 * 256;
    for (int t = idx; t < n3; t += stride) {
        int l = t / (128 * 256);
        int r = t % (128 * 256);
        int i = r / 256;
        int k = r % 256;
        d_Wgt[l * 256 * 128 + k * 128 + i] = Wg[t];
    }
}

// ---------------- node embedding ----------------
__global__ void embed_kernel(const float* __restrict__ x,
                             const float* __restrict__ W,
                             const float* __restrict__ b,
                             const float* __restrict__ lng,
                             const float* __restrict__ lnb) {
    __shared__ float red[HID];
    int n = blockIdx.x;
    int j = threadIdx.x;
    float x0 = x[n * 3 + 0], x1 = x[n * 3 + 1], x2 = x[n * 3 + 2];
    float v = b[j] + x0 * W[j * 3 + 0] + x1 * W[j * 3 + 1] + x2 * W[j * 3 + 2];
    float m = block_sum128(v, red, j) * (1.f / HID);
    float d = v - m;
    float var = block_sum128(d * d, red, j) * (1.f / HID);
    float y = d * rsqrtf(var + 1e-5f) * lng[j] + lnb[j];
    d_h[n * HID + j] = y * sigmoidf_(y);
}

// ---------------- zero scratch ----------------
__global__ void zero_aggr_kernel() {
    int idx = blockIdx.x * blockDim.x + threadIdx.x;
    int stride = gridDim.x * blockDim.x;
    for (int t = idx; t < N_NODES * HID; t += stride) d_aggr[t] = 0.f;
}
__global__ void zero_pool_kernel() {
    int idx = blockIdx.x * blockDim.x + threadIdx.x;
    if (idx < N_GRAPHS * HID) d_sums[idx] = 0.f;
    if (idx < N_GRAPHS) d_counts[idx] = 0.f;
}

// ---------------- edge MLP via tensor cores (split-bf16 3-term, LDSM feeds) ----
__global__ void __launch_bounds__(256) edge_kernel(
    const float* __restrict__ edge_attr,
    const int* __restrict__ edge_index,
    const float* __restrict__ b1_all,   // [3][256]
    const float* __restrict__ b2_all,   // [3][128]
    int l) {
    extern __shared__ __align__(16) unsigned sm[];
    unsigned* Zh = sm;                      // 64*132 words
    unsigned* Zl = sm + 64 * 132;
    int* dst_s = (int*)(sm + 2 * 64 * 132);
    int* src_s = dst_s + 64;
    float* ea_s = (float*)(src_s + 64);

    const int tid = threadIdx.x;
    const int lane = tid & 31, w = tid >> 5;
    const int e0 = blockIdx.x * ET;

    if (tid < 64) { dst_s[tid] = edge_index[N_EDGES + e0 + tid]; ea_s[tid] = edge_attr[e0 + tid]; }
    else if (tid < 128) src_s[tid - 64] = edge_index[e0 + tid - 64];
    __syncthreads();

    // gather + fp32 -> bf16 hi/lo conversion
    {
        int e = tid >> 2, q = tid & 3;
        int node = (q < 2) ? dst_s[e] : src_s[e];
        const float4* hp = (const float4*)(d_h + node * HID + (q & 1) * 64);
        unsigned* oh = Zh + e * 132 + q * 32;
        unsigned* ol = Zl + e * 132 + q * 32;
        #pragma unroll
        for (int i = 0; i < 16; ++i) {
            float4 v = hp[i];
            unsigned h0 = pk2(v.x, v.y), h1 = pk2(v.z, v.w);
            float a0 = __uint_as_float(h0 << 16), a1 = __uint_as_float(h0 & 0xFFFF0000u);
            float a2 = __uint_as_float(h1 << 16), a3 = __uint_as_float(h1 & 0xFFFF0000u);
            oh[i * 2] = h0; oh[i * 2 + 1] = h1;
            ol[i * 2] = pk2(v.x - a0, v.y - a1);
            ol[i * 2 + 1] = pk2(v.z - a2, v.w - a3);
        }
    }
    __syncthreads();

    const int r = lane >> 2, qk = lane & 3;
    // LDSM per-lane address offset: row = lane&15, k-halves split at lane 16
    const unsigned zh_base = (unsigned)__cvta_generic_to_shared(Zh);
    const unsigned zl_base = (unsigned)__cvta_generic_to_shared(Zl);
    const unsigned aoff = ((lane & 15) * 132 + ((lane >> 4) << 2)) * 4;

    // ---- GEMM1 ----
    float c[4][4][4];
    #pragma unroll
    for (int m = 0; m < 4; ++m)
        #pragma unroll
        for (int t = 0; t < 4; ++t)
            #pragma unroll
            for (int k = 0; k < 4; ++k) c[m][t][k] = 0.f;

    for (int s = 0; s < 16; ++s) {
        unsigned Ah[4][4], Al[4][4];
        #pragma unroll
        for (int m = 0; m < 4; ++m) {
            unsigned toff = aoff + (m * 16 * 132 + s * 8) * 4;
            ldsm4(Ah[m], zh_base + toff);
            ldsm4(Al[m], zl_base + toff);
        }
        #pragma unroll
        for (int t = 0; t < 4; ++t) {
            uint4 wv = d_W1f[((l * 16 + s) * 32 + (w * 4 + t)) * 32 + lane];
            #pragma unroll
            for (int m = 0; m < 4; ++m)
                mma_bf16(c[m][t], Ah[m][0], Ah[m][1], Ah[m][2], Ah[m][3], wv.x, wv.y);
            #pragma unroll
            for (int m = 0; m < 4; ++m)
                mma_bf16(c[m][t], Ah[m][0], Ah[m][1], Ah[m][2], Ah[m][3], wv.z, wv.w);
            #pragma unroll
            for (int m = 0; m < 4; ++m)
                mma_bf16(c[m][t], Al[m][0], Al[m][1], Al[m][2], Al[m][3], wv.x, wv.y);
        }
    }
    __syncthreads();   // all Z reads complete before overwrite

    // epilogue1: bias + edge_attr tail + silu -> bf16 hi/lo back into Zh/Zl
    #pragma unroll
    for (int m = 0; m < 4; ++m) {
        #pragma unroll
        for (int t = 0; t < 4; ++t) {
            int n0 = (w * 4 + t) * 8 + qk * 2;
            int elo = m * 16 + r, ehi = elo + 8;
            float bn0 = b1_all[l * 256 + n0], bn1 = b1_all[l * 256 + n0 + 1];
            float wt0 = d_W1tail[l * 256 + n0], wt1 = d_W1tail[l * 256 + n0 + 1];
            float el = ea_s[elo], eh = ea_s[ehi];
            float v00 = c[m][t][0] + bn0 + el * wt0;
            float v01 = c[m][t][1] + bn1 + el * wt1;
            float v10 = c[m][t][2] + bn0 + eh * wt0;
            float v11 = c[m][t][3] + bn1 + eh * wt1;
            v00 *= sigmoidf_(v00); v01 *= sigmoidf_(v01);
            v10 *= sigmoidf_(v10); v11 *= sigmoidf_(v11);
            int wlo = elo * 132 + (w * 4 + t) * 4 + qk;
            int whi = ehi * 132 + (w * 4 + t) * 4 + qk;
            unsigned h0 = pk2(v00, v01);
            unsigned h1 = pk2(v10, v11);
            float a0 = __uint_as_float(h0 << 16), a1 = __uint_as_float(h0 & 0xFFFF0000u);
            float a2 = __uint_as_float(h1 << 16), a3 = __uint_as_float(h1 & 0xFFFF0000u);
            Zh[wlo] = h0; Zl[wlo] = pk2(v00 - a0, v01 - a1);
            Zh[whi] = h1; Zl[whi] = pk2(v10 - a2, v11 - a3);
        }
    }
    __syncthreads();

    // ---- GEMM2 ----
    float c2[4][2][4];
    #pragma unroll
    for (int m = 0; m < 4; ++m)
        #pragma unroll
        for (int t = 0; t < 2; ++t)
            #pragma unroll
            for (int k = 0; k < 4; ++k) c2[m][t][k] = 0.f;

    for (int s = 0; s < 16; ++s) {
        unsigned Ah[4][4], Al[4][4];
        #pragma unroll
        for (int m = 0; m < 4; ++m) {
            unsigned toff = aoff + (m * 16 * 132 + s * 8) * 4;
            ldsm4(Ah[m], zh_base + toff);
            ldsm4(Al[m], zl_base + toff);
        }
        #pragma unroll
        for (int t = 0; t < 2; ++t) {
            uint4 wv = d_W2f[((l * 16 + s) * 16 + (w * 2 + t)) * 32 + lane];
            #pragma unroll
            for (int m = 0; m < 4; ++m)
                mma_bf16(c2[m][t], Ah[m][0], Ah[m][1], Ah[m][2], Ah[m][3], wv.x, wv.y);
            #pragma unroll
            for (int m = 0; m < 4; ++m)
                mma_bf16(c2[m][t], Ah[m][0], Ah[m][1], Ah[m][2], Ah[m][3], wv.z, wv.w);
            #pragma unroll
            for (int m = 0; m < 4; ++m)
                mma_bf16(c2[m][t], Al[m][0], Al[m][1], Al[m][2], Al[m][3], wv.x, wv.y);
        }
    }

    // epilogue2: bias + scatter-add
    #pragma unroll
    for (int m = 0; m < 4; ++m) {
        #pragma unroll
        for (int t = 0; t < 2; ++t) {
            int i0 = (w * 2 + t) * 8 + qk * 2;
            int elo = m * 16 + r, ehi = elo + 8;
            float bi0 = b2_all[l * 128 + i0], bi1 = b2_all[l * 128 + i0 + 1];
            int dlo = dst_s[elo], dhi = dst_s[ehi];
            atomicAdd(&d_aggr[dlo * HID + i0],     c2[m][t][0] + bi0);
            atomicAdd(&d_aggr[dlo * HID + i0 + 1], c2[m][t][1] + bi1);
            atomicAdd(&d_aggr[dhi * HID + i0],     c2[m][t][2] + bi0);
            atomicAdd(&d_aggr[dhi * HID + i0 + 1], c2[m][t][3] + bi1);
        }
    }
}

// ---------------- gated node update + residual + LN (NB nodes/block) --------
__global__ void __launch_bounds__(HID) node_kernel(
    const float* __restrict__ gb_all,
    const float* __restrict__ lng_all,
    const float* __restrict__ lnb_all,
    int l) {
    __shared__ float hn[NB][HID], an[NB][HID], red[NB][HID];
    int n0 = blockIdx.x * NB;
    int j = threadIdx.x;
    #pragma unroll
    for (int n = 0; n < NB; ++n) {
        hn[n][j] = d_h[(n0 + n) * HID + j];
        an[n][j] = d_aggr[(n0 + n) * HID + j];
    }
    __syncthreads();

    const float* Wg = d_Wgt + l * 256 * HID;
    float g[NB];
    float gb0 = gb_all[l * HID + j];
    #pragma unroll
    for (int n = 0; n < NB; ++n) g[n] = gb0;
    for (int k = 0; k < HID; ++k) {
        float wv = Wg[k * HID + j];
        #pragma unroll
        for (int n = 0; n < NB; ++n) g[n] = fmaf(hn[n][k], wv, g[n]);
    }
    for (int k = 0; k < HID; ++k) {
        float wv = Wg[(HID + k) * HID + j];
        #pragma unroll
        for (int n = 0; n < NB; ++n) g[n] = fmaf(an[n][k], wv, g[n]);
    }

    float t[NB];
    #pragma unroll
    for (int n = 0; n < NB; ++n) {
        float gs = sigmoidf_(g[n]);
        float hnew = gs * an[n][j] + (1.f - gs) * hn[n][j];
        t[n] = hn[n][j] + hnew;
        red[n][j] = t[n];
    }
    __syncthreads();
    #pragma unroll
    for (int s = 64; s > 0; s >>= 1) {
        if (j < s)
            #pragma unroll
            for (int n = 0; n < NB; ++n) red[n][j] += red[n][j + s];
        __syncthreads();
    }
    float mean[NB];
    #pragma unroll
    for (int n = 0; n < NB; ++n) mean[n] = red[n][0] * (1.f / HID);
    __syncthreads();
    float dd[NB];
    #pragma unroll
    for (int n = 0; n < NB; ++n) { dd[n] = t[n] - mean[n]; red[n][j] = dd[n] * dd[n]; }
    __syncthreads();
    #pragma unroll
    for (int s = 64; s > 0; s >>= 1) {
        if (j < s)
            #pragma unroll
            for (int n = 0; n < NB; ++n) red[n][j] += red[n][j + s];
        __syncthreads();
    }
    float lg = lng_all[l * HID + j], lb = lnb_all[l * HID + j];
    #pragma unroll
    for (int n = 0; n < NB; ++n) {
        float var = red[n][0] * (1.f / HID);
        d_h[(n0 + n) * HID + j] = dd[n] * rsqrtf(var + 1e-5f) * lg + lb;
    }
}

// ---------------- pooling ----------------
__global__ void pool_kernel(const int* __restrict__ batch) {
    int n = blockIdx.x;
    int j = threadIdx.x;
    int g = batch[n];
    atomicAdd(&d_sums[g * HID + j], d_h[n * HID + j]);
    if (j == 0) atomicAdd(&d_counts[g], 1.f);
}

// ---------------- x_global + projector ----------------
__global__ void final_kernel(const float* __restrict__ W1, const float* __restrict__ b1,
                             const float* __restrict__ g1, const float* __restrict__ bb1,
                             const float* __restrict__ W2, const float* __restrict__ b2,
                             const float* __restrict__ g2, const float* __restrict__ bb2,
                             float* __restrict__ out) {
    __shared__ float xg[HID], p[HID], red[HID];
    int gr = blockIdx.x;
    int j = threadIdx.x;

    float c = d_counts[gr];
    float scale = 1.f / fmaxf(c, 1.f) + 1.f / (c + 1e-6f);
    float v = d_sums[gr * HID + j] * scale;
    xg[j] = v;
    out[N_GRAPHS * LAT + gr * HID + j] = v;
    __syncthreads();

    float a = b1[j];
    #pragma unroll 4
    for (int k = 0; k < HID; ++k) a = fmaf(xg[k], W1[j * HID + k], a);
    float m = block_sum128(a, red, j) * (1.f / HID);
    float d = a - m;
    float var = block_sum128(d * d, red, j) * (1.f / HID);
    a = d * rsqrtf(var + 1e-5f) * g1[j] + bb1[j];
    a = a * sigmoidf_(a);
    p[j] = a;
    __syncthreads();

    float z = 0.f;
    if (j < LAT) {
        z = b2[j];
        #pragma unroll 4
        for (int k = 0; k < HID; ++k) z = fmaf(p[k], W2[j * HID + k], z);
    }
    float m2 = block_sum128((j < LAT) ? z : 0.f, red, j) * (1.f / LAT);
    float d2 = z - m2;
    float var2 = block_sum128((j < LAT) ? d2 * d2 : 0.f, red, j) * (1.f / LAT);
    if (j < LAT)
        out[gr * LAT + j] = d2 * rsqrtf(var2 + 1e-5f) * g2[j] + bb2[j];
}

// ---------------- launch ----------------
extern "C" void kernel_launch(void* const* d_in, const int* in_sizes, int n_in,
                              void* d_out, int out_size) {
    const float* x     = (const float*)d_in[0];
    const float* ea    = (const float*)d_in[1];
    const int*   ei    = (const int*)  d_in[2];
    const int*   batch = (const int*)  d_in[3];
    const float* embW  = (const float*)d_in[4];
    const float* embb  = (const float*)d_in[5];
    const float* embg  = (const float*)d_in[6];
    const float* emblb = (const float*)d_in[7];
    const float* m1W   = (const float*)d_in[8];
    const float* m1b   = (const float*)d_in[9];
    const float* m2W   = (const float*)d_in[10];
    const float* m2b   = (const float*)d_in[11];
    const float* gW    = (const float*)d_in[12];
    const float* gb    = (const float*)d_in[13];
    const float* lng   = (const float*)d_in[14];
    const float* lnb   = (const float*)d_in[15];
    const float* p1W   = (const float*)d_in[16];
    const float* p1b   = (const float*)d_in[17];
    const float* pl1g  = (const float*)d_in[18];
    const float* pl1b  = (const float*)d_in[19];
    const float* p2W   = (const float*)d_in[20];
    const float* p2b   = (const float*)d_in[21];
    const float* pl2g  = (const float*)d_in[22];
    const float* pl2b  = (const float*)d_in[23];
    float* out = (float*)d_out;

    const int smem_bytes = 2 * 64 * 132 * 4 + 3 * 64 * 4;   // 68352
    cudaFuncSetAttribute(edge_kernel, cudaFuncAttributeMaxDynamicSharedMemorySize, smem_bytes);

    pack_kernel<<<384, 256>>>(m1W, m2W, gW);
    embed_kernel<<<N_NODES, HID>>>(x, embW, embb, embg, emblb);

    for (int l = 0; l < NLAY; ++l) {
        zero_aggr_kernel<<<640, 256>>>();
        edge_kernel<<<N_EDGES / ET, 256, smem_bytes>>>(ea, ei, m1b, m2b, l);
        node_kernel<<<N_NODES / NB, HID>>>(gb, lng, lnb, l);
    }

    zero_pool_kernel<<<33, 256>>>();
    pool_kernel<<<N_NODES, HID>>>(batch);
    final_kernel<<<N_GRAPHS, HID>>>(p1W, p1b, pl1g, pl1b, p2W, p2b, pl2g, pl2b, out);
}

// round 7
// speedup vs baseline: 1.2937x; 1.2937x over previous
#include <cuda_runtime.h>
#include <cuda_bf16.h>
#include <math.h>

#define N_NODES 10000
#define N_EDGES 160000
#define N_GRAPHS 64
#define HID 128
#define LAT 64
#define NLAY 3
#define ET 64          // edges per block in the edge kernel
#define NB 8           // nodes per block in node_kernel

// ---------------- device scratch (no allocations allowed) ----------------
__device__ float d_h[N_NODES * HID];
__device__ float d_aggr[N_NODES * HID];
// B-fragment packed weights: per (layer, kstep, ntile, lane) a uint4 {hi01, hi89, lo01, lo89}
__device__ uint4 d_W1f[NLAY * 16 * 32 * 32];   // GEMM1: K=256 (16 steps), N=256 (32 ntiles)
__device__ uint4 d_W2f[NLAY * 16 * 16 * 32];   // GEMM2: K=256 (16 steps), N=128 (16 ntiles)
__device__ float d_W1tail[NLAY * 256];         // k=256 column (edge_attr weight)
__device__ float d_Wgt[NLAY * 256 * HID];      // gate_W transposed
__device__ float d_sums[N_GRAPHS * HID];
__device__ float d_counts[N_GRAPHS];

__device__ __forceinline__ float sigmoidf_(float v) {
    return 1.f / (1.f + __expf(-v));
}
// pack two floats into bf16x2 (lo = first element)
__device__ __forceinline__ unsigned pk2(float lo, float hi) {
    unsigned r;
    asm("cvt.rn.bf16x2.f32 %0, %1, %2;" : "=r"(r) : "f"(hi), "f"(lo));
    return r;
}
__device__ __forceinline__ void mma_bf16(float c[4],
                                         unsigned a0, unsigned a1, unsigned a2, unsigned a3,
                                         unsigned b0, unsigned b1) {
    asm("mma.sync.aligned.m16n8k16.row.col.f32.bf16.bf16.f32 "
        "{%0,%1,%2,%3}, {%4,%5,%6,%7}, {%8,%9}, {%0,%1,%2,%3};"
        : "+f"(c[0]), "+f"(c[1]), "+f"(c[2]), "+f"(c[3])
        : "r"(a0), "r"(a1), "r"(a2), "r"(a3), "r"(b0), "r"(b1));
}
__device__ __forceinline__ void ldsm4(unsigned r[4], unsigned addr) {
    asm volatile("ldmatrix.sync.aligned.m8n8.x4.shared.b16 {%0,%1,%2,%3}, [%4];"
        : "=r"(r[0]), "=r"(r[1]), "=r"(r[2]), "=r"(r[3]) : "r"(addr));
}

__device__ __forceinline__ float block_sum128(float v, float* red, int j) {
    red[j] = v;
    __syncthreads();
    #pragma unroll
    for (int s = 64; s > 0; s >>= 1) {
        if (j < s) red[j] += red[j + s];
        __syncthreads();
    }
    float r = red[0];
    __syncthreads();
    return r;
}

// ---------------- weight fragment packing (run once per launch) ----------------
__global__ void pack_kernel(const float* __restrict__ W1,   // [3][256][257]
                            const float* __restrict__ W2,   // [3][128][256]
                            const float* __restrict__ Wg) { // [3][128][256]
    int idx = blockIdx.x * blockDim.x + threadIdx.x;
    int stride = gridDim.x * blockDim.x;
    const int n1 = NLAY * 16 * 32 * 32;
    for (int t = idx; t < n1; t += stride) {
        int l = t / (16 * 32 * 32);
        int r = t % (16 * 32 * 32);
        int s = r / (32 * 32);
        int r2 = r % (32 * 32);
        int tt = r2 / 32;
        int lane = r2 % 32;
        int n = tt * 8 + lane / 4;
        int k0 = s * 16 + (lane % 4) * 2;
        const float* row = W1 + (l * 256 + n) * 257;
        float f0 = row[k0], f1 = row[k0 + 1], f2 = row[k0 + 8], f3 = row[k0 + 9];
        unsigned h01 = pk2(f0, f1);
        unsigned h89 = pk2(f2, f3);
        float a0 = __uint_as_float(h01 << 16), a1 = __uint_as_float(h01 & 0xFFFF0000u);
        float a2 = __uint_as_float(h89 << 16), a3 = __uint_as_float(h89 & 0xFFFF0000u);
        uint4 o;
        o.x = h01; o.y = h89;
        o.z = pk2(f0 - a0, f1 - a1);
        o.w = pk2(f2 - a2, f3 - a3);
        d_W1f[t] = o;
    }
    const int n2 = NLAY * 16 * 16 * 32;
    for (int t = idx; t < n2; t += stride) {
        int l = t / (16 * 16 * 32);
        int r = t % (16 * 16 * 32);
        int s = r / (16 * 32);
        int r2 = r % (16 * 32);
        int tt = r2 / 32;
        int lane = r2 % 32;
        int n = tt * 8 + lane / 4;
        int k0 = s * 16 + (lane % 4) * 2;
        const float* row = W2 + (l * 128 + n) * 256;
        float f0 = row[k0], f1 = row[k0 + 1], f2 = row[k0 + 8], f3 = row[k0 + 9];
        unsigned h01 = pk2(f0, f1);
        unsigned h89 = pk2(f2, f3);
        float a0 = __uint_as_float(h01 << 16), a1 = __uint_as_float(h01 & 0xFFFF0000u);
        float a2 = __uint_as_float(h89 << 16), a3 = __uint_as_float(h89 & 0xFFFF0000u);
        uint4 o;
        o.x = h01; o.y = h89;
        o.z = pk2(f0 - a0, f1 - a1);
        o.w = pk2(f2 - a2, f3 - a3);
        d_W2f[t] = o;
    }
    for (int t = idx; t < NLAY * 256; t += stride) {
        int l = t / 256;
        int j = t % 256;
        d_W1tail[t] = W1[(l * 256 + j) * 257 + 256];
    }
    const int n3 = NLAY * 128 * 256;
    for (int t = idx; t < n3; t += stride) {
        int l = t / (128 * 256);
        int r = t % (128 * 256);
        int i = r / 256;
        int k = r % 256;
        d_Wgt[l * 256 * 128 + k * 128 + i] = Wg[t];
    }
}

// ---------------- node embedding ----------------
__global__ void embed_kernel(const float* __restrict__ x,
                             const float* __restrict__ W,
                             const float* __restrict__ b,
                             const float* __restrict__ lng,
                             const float* __restrict__ lnb) {
    __shared__ float red[HID];
    int n = blockIdx.x;
    int j = threadIdx.x;
    float x0 = x[n * 3 + 0], x1 = x[n * 3 + 1], x2 = x[n * 3 + 2];
    float v = b[j] + x0 * W[j * 3 + 0] + x1 * W[j * 3 + 1] + x2 * W[j * 3 + 2];
    float m = block_sum128(v, red, j) * (1.f / HID);
    float d = v - m;
    float var = block_sum128(d * d, red, j) * (1.f / HID);
    float y = d * rsqrtf(var + 1e-5f) * lng[j] + lnb[j];
    d_h[n * HID + j] = y * sigmoidf_(y);
}

// ---------------- zero scratch ----------------
__global__ void zero_aggr_kernel() {
    int idx = blockIdx.x * blockDim.x + threadIdx.x;
    int stride = gridDim.x * blockDim.x;
    for (int t = idx; t < N_NODES * HID; t += stride) d_aggr[t] = 0.f;
}
__global__ void zero_pool_kernel() {
    int idx = blockIdx.x * blockDim.x + threadIdx.x;
    if (idx < N_GRAPHS * HID) d_sums[idx] = 0.f;
    if (idx < N_GRAPHS) d_counts[idx] = 0.f;
}

// ---------------- edge MLP via tensor cores (split-bf16 3-term, LDSM feeds) ----
// __launch_bounds__(256, 2): cap at 128 regs so 2 CTAs stay resident per SM.
__global__ void __launch_bounds__(256, 2) edge_kernel(
    const float* __restrict__ edge_attr,
    const int* __restrict__ edge_index,
    const float* __restrict__ b1_all,   // [3][256]
    const float* __restrict__ b2_all,   // [3][128]
    int l) {
    extern __shared__ __align__(16) unsigned sm[];
    unsigned* Zh = sm;                      // 64*132 words
    unsigned* Zl = sm + 64 * 132;
    int* dst_s = (int*)(sm + 2 * 64 * 132);
    int* src_s = dst_s + 64;
    float* ea_s = (float*)(src_s + 64);

    const int tid = threadIdx.x;
    const int lane = tid & 31, w = tid >> 5;
    const int e0 = blockIdx.x * ET;

    if (tid < 64) { dst_s[tid] = edge_index[N_EDGES + e0 + tid]; ea_s[tid] = edge_attr[e0 + tid]; }
    else if (tid < 128) src_s[tid - 64] = edge_index[e0 + tid - 64];
    __syncthreads();

    // gather + fp32 -> bf16 hi/lo conversion
    {
        int e = tid >> 2, q = tid & 3;
        int node = (q < 2) ? dst_s[e] : src_s[e];
        const float4* hp = (const float4*)(d_h + node * HID + (q & 1) * 64);
        unsigned* oh = Zh + e * 132 + q * 32;
        unsigned* ol = Zl + e * 132 + q * 32;
        #pragma unroll
        for (int i = 0; i < 16; ++i) {
            float4 v = hp[i];
            unsigned h0 = pk2(v.x, v.y), h1 = pk2(v.z, v.w);
            float a0 = __uint_as_float(h0 << 16), a1 = __uint_as_float(h0 & 0xFFFF0000u);
            float a2 = __uint_as_float(h1 << 16), a3 = __uint_as_float(h1 & 0xFFFF0000u);
            oh[i * 2] = h0; oh[i * 2 + 1] = h1;
            ol[i * 2] = pk2(v.x - a0, v.y - a1);
            ol[i * 2 + 1] = pk2(v.z - a2, v.w - a3);
        }
    }
    __syncthreads();

    const int r = lane >> 2, qk = lane & 3;
    // LDSM per-lane address offset: row = lane&15, k-halves split at lane 16
    const unsigned zh_base = (unsigned)__cvta_generic_to_shared(Zh);
    const unsigned zl_base = (unsigned)__cvta_generic_to_shared(Zl);
    const unsigned aoff = ((lane & 15) * 132 + ((lane >> 4) << 2)) * 4;

    // ---- GEMM1 ----
    float c[4][4][4];
    #pragma unroll
    for (int m = 0; m < 4; ++m)
        #pragma unroll
        for (int t = 0; t < 4; ++t)
            #pragma unroll
            for (int k = 0; k < 4; ++k) c[m][t][k] = 0.f;

    for (int s = 0; s < 16; ++s) {
        unsigned Ah[4][4], Al[4][4];
        #pragma unroll
        for (int m = 0; m < 4; ++m) {
            unsigned toff = aoff + (m * 16 * 132 + s * 8) * 4;
            ldsm4(Ah[m], zh_base + toff);
            ldsm4(Al[m], zl_base + toff);
        }
        #pragma unroll
        for (int t = 0; t < 4; ++t) {
            uint4 wv = d_W1f[((l * 16 + s) * 32 + (w * 4 + t)) * 32 + lane];
            #pragma unroll
            for (int m = 0; m < 4; ++m)
                mma_bf16(c[m][t], Ah[m][0], Ah[m][1], Ah[m][2], Ah[m][3], wv.x, wv.y);
            #pragma unroll
            for (int m = 0; m < 4; ++m)
                mma_bf16(c[m][t], Ah[m][0], Ah[m][1], Ah[m][2], Ah[m][3], wv.z, wv.w);
            #pragma unroll
            for (int m = 0; m < 4; ++m)
                mma_bf16(c[m][t], Al[m][0], Al[m][1], Al[m][2], Al[m][3], wv.x, wv.y);
        }
    }
    __syncthreads();   // all Z reads complete before overwrite

    // epilogue1: bias + edge_attr tail + silu -> bf16 hi/lo back into Zh/Zl
    #pragma unroll
    for (int m = 0; m < 4; ++m) {
        #pragma unroll
        for (int t = 0; t < 4; ++t) {
            int n0 = (w * 4 + t) * 8 + qk * 2;
            int elo = m * 16 + r, ehi = elo + 8;
            float bn0 = b1_all[l * 256 + n0], bn1 = b1_all[l * 256 + n0 + 1];
            float wt0 = d_W1tail[l * 256 + n0], wt1 = d_W1tail[l * 256 + n0 + 1];
            float el = ea_s[elo], eh = ea_s[ehi];
            float v00 = c[m][t][0] + bn0 + el * wt0;
            float v01 = c[m][t][1] + bn1 + el * wt1;
            float v10 = c[m][t][2] + bn0 + eh * wt0;
            float v11 = c[m][t][3] + bn1 + eh * wt1;
            v00 *= sigmoidf_(v00); v01 *= sigmoidf_(v01);
            v10 *= sigmoidf_(v10); v11 *= sigmoidf_(v11);
            int wlo = elo * 132 + (w * 4 + t) * 4 + qk;
            int whi = ehi * 132 + (w * 4 + t) * 4 + qk;
            unsigned h0 = pk2(v00, v01);
            unsigned h1 = pk2(v10, v11);
            float a0 = __uint_as_float(h0 << 16), a1 = __uint_as_float(h0 & 0xFFFF0000u);
            float a2 = __uint_as_float(h1 << 16), a3 = __uint_as_float(h1 & 0xFFFF0000u);
            Zh[wlo] = h0; Zl[wlo] = pk2(v00 - a0, v01 - a1);
            Zh[whi] = h1; Zl[whi] = pk2(v10 - a2, v11 - a3);
        }
    }
    __syncthreads();

    // ---- GEMM2 ----
    float c2[4][2][4];
    #pragma unroll
    for (int m = 0; m < 4; ++m)
        #pragma unroll
        for (int t = 0; t < 2; ++t)
            #pragma unroll
            for (int k = 0; k < 4; ++k) c2[m][t][k] = 0.f;

    for (int s = 0; s < 16; ++s) {
        unsigned Ah[4][4], Al[4][4];
        #pragma unroll
        for (int m = 0; m < 4; ++m) {
            unsigned toff = aoff + (m * 16 * 132 + s * 8) * 4;
            ldsm4(Ah[m], zh_base + toff);
            ldsm4(Al[m], zl_base + toff);
        }
        #pragma unroll
        for (int t = 0; t < 2; ++t) {
            uint4 wv = d_W2f[((l * 16 + s) * 16 + (w * 2 + t)) * 32 + lane];
            #pragma unroll
            for (int m = 0; m < 4; ++m)
                mma_bf16(c2[m][t], Ah[m][0], Ah[m][1], Ah[m][2], Ah[m][3], wv.x, wv.y);
            #pragma unroll
            for (int m = 0; m < 4; ++m)
                mma_bf16(c2[m][t], Ah[m][0], Ah[m][1], Ah[m][2], Ah[m][3], wv.z, wv.w);
            #pragma unroll
            for (int m = 0; m < 4; ++m)
                mma_bf16(c2[m][t], Al[m][0], Al[m][1], Al[m][2], Al[m][3], wv.x, wv.y);
        }
    }

    // epilogue2: bias + scatter-add
    #pragma unroll
    for (int m = 0; m < 4; ++m) {
        #pragma unroll
        for (int t = 0; t < 2; ++t) {
            int i0 = (w * 2 + t) * 8 + qk * 2;
            int elo = m * 16 + r, ehi = elo + 8;
            float bi0 = b2_all[l * 128 + i0], bi1 = b2_all[l * 128 + i0 + 1];
            int dlo = dst_s[elo], dhi = dst_s[ehi];
            atomicAdd(&d_aggr[dlo * HID + i0],     c2[m][t][0] + bi0);
            atomicAdd(&d_aggr[dlo * HID + i0 + 1], c2[m][t][1] + bi1);
            atomicAdd(&d_aggr[dhi * HID + i0],     c2[m][t][2] + bi0);
            atomicAdd(&d_aggr[dhi * HID + i0 + 1], c2[m][t][3] + bi1);
        }
    }
}

// ---------------- gated node update + residual + LN (NB nodes/block) --------
__global__ void __launch_bounds__(HID) node_kernel(
    const float* __restrict__ gb_all,
    const float* __restrict__ lng_all,
    const float* __restrict__ lnb_all,
    int l) {
    __shared__ float hn[NB][HID], an[NB][HID], red[NB][HID];
    int n0 = blockIdx.x * NB;
    int j = threadIdx.x;
    #pragma unroll
    for (int n = 0; n < NB; ++n) {
        hn[n][j] = d_h[(n0 + n) * HID + j];
        an[n][j] = d_aggr[(n0 + n) * HID + j];
    }
    __syncthreads();

    const float* Wg = d_Wgt + l * 256 * HID;
    float g[NB];
    float gb0 = gb_all[l * HID + j];
    #pragma unroll
    for (int n = 0; n < NB; ++n) g[n] = gb0;
    for (int k = 0; k < HID; ++k) {
        float wv = Wg[k * HID + j];
        #pragma unroll
        for (int n = 0; n < NB; ++n) g[n] = fmaf(hn[n][k], wv, g[n]);
    }
    for (int k = 0; k < HID; ++k) {
        float wv = Wg[(HID + k) * HID + j];
        #pragma unroll
        for (int n = 0; n < NB; ++n) g[n] = fmaf(an[n][k], wv, g[n]);
    }

    float t[NB];
    #pragma unroll
    for (int n = 0; n < NB; ++n) {
        float gs = sigmoidf_(g[n]);
        float hnew = gs * an[n][j] + (1.f - gs) * hn[n][j];
        t[n] = hn[n][j] + hnew;
        red[n][j] = t[n];
    }
    __syncthreads();
    #pragma unroll
    for (int s = 64; s > 0; s >>= 1) {
        if (j < s)
            #pragma unroll
            for (int n = 0; n < NB; ++n) red[n][j] += red[n][j + s];
        __syncthreads();
    }
    float mean[NB];
    #pragma unroll
    for (int n = 0; n < NB; ++n) mean[n] = red[n][0] * (1.f / HID);
    __syncthreads();
    float dd[NB];
    #pragma unroll
    for (int n = 0; n < NB; ++n) { dd[n] = t[n] - mean[n]; red[n][j] = dd[n] * dd[n]; }
    __syncthreads();
    #pragma unroll
    for (int s = 64; s > 0; s >>= 1) {
        if (j < s)
            #pragma unroll
            for (int n = 0; n < NB; ++n) red[n][j] += red[n][j + s];
        __syncthreads();
    }
    float lg = lng_all[l * HID + j], lb = lnb_all[l * HID + j];
    #pragma unroll
    for (int n = 0; n < NB; ++n) {
        float var = red[n][0] * (1.f / HID);
        d_h[(n0 + n) * HID + j] = dd[n] * rsqrtf(var + 1e-5f) * lg + lb;
    }
}

// ---------------- pooling ----------------
__global__ void pool_kernel(const int* __restrict__ batch) {
    int n = blockIdx.x;
    int j = threadIdx.x;
    int g = batch[n];
    atomicAdd(&d_sums[g * HID + j], d_h[n * HID + j]);
    if (j == 0) atomicAdd(&d_counts[g], 1.f);
}

// ---------------- x_global + projector ----------------
__global__ void final_kernel(const float* __restrict__ W1, const float* __restrict__ b1,
                             const float* __restrict__ g1, const float* __restrict__ bb1,
                             const float* __restrict__ W2, const float* __restrict__ b2,
                             const float* __restrict__ g2, const float* __restrict__ bb2,
                             float* __restrict__ out) {
    __shared__ float xg[HID], p[HID], red[HID];
    int gr = blockIdx.x;
    int j = threadIdx.x;

    float c = d_counts[gr];
    float scale = 1.f / fmaxf(c, 1.f) + 1.f / (c + 1e-6f);
    float v = d_sums[gr * HID + j] * scale;
    xg[j] = v;
    out[N_GRAPHS * LAT + gr * HID + j] = v;
    __syncthreads();

    float a = b1[j];
    #pragma unroll 4
    for (int k = 0; k < HID; ++k) a = fmaf(xg[k], W1[j * HID + k], a);
    float m = block_sum128(a, red, j) * (1.f / HID);
    float d = a - m;
    float var = block_sum128(d * d, red, j) * (1.f / HID);
    a = d * rsqrtf(var + 1e-5f) * g1[j] + bb1[j];
    a = a * sigmoidf_(a);
    p[j] = a;
    __syncthreads();

    float z = 0.f;
    if (j < LAT) {
        z = b2[j];
        #pragma unroll 4
        for (int k = 0; k < HID; ++k) z = fmaf(p[k], W2[j * HID + k], z);
    }
    float m2 = block_sum128((j < LAT) ? z : 0.f, red, j) * (1.f / LAT);
    float d2 = z - m2;
    float var2 = block_sum128((j < LAT) ? d2 * d2 : 0.f, red, j) * (1.f / LAT);
    if (j < LAT)
        out[gr * LAT + j] = d2 * rsqrtf(var2 + 1e-5f) * g2[j] + bb2[j];
}

// ---------------- launch ----------------
extern "C" void kernel_launch(void* const* d_in, const int* in_sizes, int n_in,
                              void* d_out, int out_size) {
    const float* x     = (const float*)d_in[0];
    const float* ea    = (const float*)d_in[1];
    const int*   ei    = (const int*)  d_in[2];
    const int*   batch = (const int*)  d_in[3];
    const float* embW  = (const float*)d_in[4];
    const float* embb  = (const float*)d_in[5];
    const float* embg  = (const float*)d_in[6];
    const float* emblb = (const float*)d_in[7];
    const float* m1W   = (const float*)d_in[8];
    const float* m1b   = (const float*)d_in[9];
    const float* m2W   = (const float*)d_in[10];
    const float* m2b   = (const float*)d_in[11];
    const float* gW    = (const float*)d_in[12];
    const float* gb    = (const float*)d_in[13];
    const float* lng   = (const float*)d_in[14];
    const float* lnb   = (const float*)d_in[15];
    const float* p1W   = (const float*)d_in[16];
    const float* p1b   = (const float*)d_in[17];
    const float* pl1g  = (const float*)d_in[18];
    const float* pl1b  = (const float*)d_in[19];
    const float* p2W   = (const float*)d_in[20];
    const float* p2b   = (const float*)d_in[21];
    const float* pl2g  = (const float*)d_in[22];
    const float* pl2b  = (const float*)d_in[23];
    float* out = (float*)d_out;

    const int smem_bytes = 2 * 64 * 132 * 4 + 3 * 64 * 4;   // 68352
    cudaFuncSetAttribute(edge_kernel, cudaFuncAttributeMaxDynamicSharedMemorySize, smem_bytes);

    pack_kernel<<<384, 256>>>(m1W, m2W, gW);
    embed_kernel<<<N_NODES, HID>>>(x, embW, embb, embg, emblb);

    for (int l = 0; l < NLAY; ++l) {
        zero_aggr_kernel<<<640, 256>>>();
        edge_kernel<<<N_EDGES / ET, 256, smem_bytes>>>(ea, ei, m1b, m2b, l);
        node_kernel<<<N_NODES / NB, HID>>>(gb, lng, lnb, l);
    }

    zero_pool_kernel<<<33, 256>>>();
    pool_kernel<<<N_NODES, HID>>>(batch);
    final_kernel<<<N_GRAPHS, HID>>>(p1W, p1b, pl1g, pl1b, p2W, p2b, pl2g, pl2b, out);
}